// round 4
// baseline (speedup 1.0000x reference)
#include <cuda_runtime.h>
#include <math.h>

// Problem constants (fixed shapes from reference)
#define HW     3136     // 56*56
#define HW4    784      // HW / 4 (float4 chunks per row)
#define B_SZ   64
#define C_IN   512
#define A_DIM  32
#define C_OUT  512
#define BN_EPS 1e-5f
#define BLOCKS_PER_B 64   // 64 blocks x 8 warps = 512 rows per batch

// Scratch for pooled means: [B, C_in]
__device__ float g_pooled[B_SZ * C_IN];
// Per-batch completion counters. Never reset: finisher = (old+1) % 64 == 0.
__device__ unsigned int g_cnt[B_SZ];

// ---------------------------------------------------------------------------
// Fused kernel: global average pool + per-batch FC chain.
//  Pool: one warp per (b,c) row, float4 coalesced loads, shuffle reduce.
//  Grid = 4096 blocks of 256 threads; blocks [b*64, (b+1)*64) serve batch b.
//  The block that completes batch b's counter runs the FC for that batch:
//    h[a]  = relu(BN(dot(pooled, fc_w[a])))        a in [0,32)
//    ch[c] = sigmoid(dot(h, channel_fc_w[c]) + b)  c in [0,512)
//    f[o]  = sigmoid(dot(h, filter_fc_w[o]) + b)   o in [0,512)
// ---------------------------------------------------------------------------
__global__ __launch_bounds__(256) void fused_kernel(
    const float* __restrict__ x,
    const float* __restrict__ fc_w,         // [A, C_in]
    const float* __restrict__ bn_gamma,     // [A]
    const float* __restrict__ bn_beta,      // [A]
    const float* __restrict__ bn_mean,      // [A]
    const float* __restrict__ bn_var,       // [A]
    const float* __restrict__ channel_fc_w, // [C_in, A]
    const float* __restrict__ channel_fc_b, // [C_in]
    const float* __restrict__ filter_fc_w,  // [C_out, A]
    const float* __restrict__ filter_fc_b,  // [C_out]
    float* __restrict__ out)                // [2 * B * 512]
{
    const int tid  = threadIdx.x;
    const int warp = tid >> 5;
    const int lane = tid & 31;
    const int b    = blockIdx.x >> 6;             // 64 blocks per batch

    // ---------------- pool phase: this warp's row ----------------
    const int gwarp = blockIdx.x * 8 + warp;      // global row = (b, c)
    const float4* __restrict__ row =
        reinterpret_cast<const float4*>(x + (size_t)gwarp * HW);

    float s0 = 0.f, s1 = 0.f;
    int i = lane;
    #pragma unroll 4
    for (; i + 32 < HW4; i += 64) {
        float4 v0 = __ldg(&row[i]);
        float4 v1 = __ldg(&row[i + 32]);
        s0 += (v0.x + v0.y) + (v0.z + v0.w);
        s1 += (v1.x + v1.y) + (v1.z + v1.w);
    }
    if (i < HW4) {
        float4 v0 = __ldg(&row[i]);
        s0 += (v0.x + v0.y) + (v0.z + v0.w);
    }
    float s = s0 + s1;
    #pragma unroll
    for (int off = 16; off > 0; off >>= 1)
        s += __shfl_xor_sync(0xFFFFFFFFu, s, off);
    if (lane == 0)
        g_pooled[gwarp] = s * (1.0f / (float)HW);

    // ---------------- completion handshake ----------------
    __shared__ int s_last;
    __syncthreads();                 // all 8 rows of this block written
    if (tid == 0) {
        __threadfence();             // publish g_pooled writes
        unsigned int old = atomicAdd(&g_cnt[b], 1u);
        s_last = (((old + 1u) & (BLOCKS_PER_B - 1u)) == 0u);
    }
    __syncthreads();
    if (!s_last) return;

    // ---------------- FC phase (one block per batch) ----------------
    __threadfence();                 // acquire other blocks' g_pooled writes

    // 16B alignment REQUIRED: these are read via float4 (LDS.128).
    __shared__ __align__(16) float s_pooled[C_IN];
    __shared__ __align__(16) float s_h[A_DIM];

    s_pooled[tid]       = g_pooled[b * C_IN + tid];
    s_pooled[tid + 256] = g_pooled[b * C_IN + tid + 256];
    __syncthreads();

    // h: warp w computes a = w + 8k, k = 0..3 (warp-parallel dots of 512)
    const float4* __restrict__ sp4 = reinterpret_cast<const float4*>(s_pooled);
    #pragma unroll
    for (int k = 0; k < 4; ++k) {
        const int a = warp + k * 8;
        const float4* __restrict__ w4 =
            reinterpret_cast<const float4*>(fc_w + a * C_IN);
        float acc = 0.f;
        #pragma unroll
        for (int j = 0; j < 4; ++j) {
            float4 wv = __ldg(&w4[lane + 32 * j]);
            float4 pv = sp4[lane + 32 * j];
            acc = fmaf(wv.x, pv.x, acc);
            acc = fmaf(wv.y, pv.y, acc);
            acc = fmaf(wv.z, pv.z, acc);
            acc = fmaf(wv.w, pv.w, acc);
        }
        #pragma unroll
        for (int off = 16; off > 0; off >>= 1)
            acc += __shfl_xor_sync(0xFFFFFFFFu, acc, off);
        if (lane == 0) {
            float inv_std = rsqrtf(bn_var[a] + BN_EPS);
            float hv = (acc - bn_mean[a]) * (bn_gamma[a] * inv_std) + bn_beta[a];
            s_h[a] = fmaxf(hv, 0.f);
        }
    }
    __syncthreads();

    // channel + filter attention: thread t handles c = t and c = t+256
    #pragma unroll
    for (int k = 0; k < 2; ++k) {
        const int c = tid + k * 256;
        {
            const float4* __restrict__ w4 =
                reinterpret_cast<const float4*>(channel_fc_w + c * A_DIM);
            float acc = channel_fc_b[c];
            #pragma unroll
            for (int j = 0; j < 8; ++j) {
                float4 wv = __ldg(&w4[j]);
                acc = fmaf(s_h[4 * j + 0], wv.x, acc);
                acc = fmaf(s_h[4 * j + 1], wv.y, acc);
                acc = fmaf(s_h[4 * j + 2], wv.z, acc);
                acc = fmaf(s_h[4 * j + 3], wv.w, acc);
            }
            out[b * C_IN + c] = 1.0f / (1.0f + expf(-acc));
        }
        {
            const float4* __restrict__ w4 =
                reinterpret_cast<const float4*>(filter_fc_w + c * A_DIM);
            float acc = filter_fc_b[c];
            #pragma unroll
            for (int j = 0; j < 8; ++j) {
                float4 wv = __ldg(&w4[j]);
                acc = fmaf(s_h[4 * j + 0], wv.x, acc);
                acc = fmaf(s_h[4 * j + 1], wv.y, acc);
                acc = fmaf(s_h[4 * j + 2], wv.z, acc);
                acc = fmaf(s_h[4 * j + 3], wv.w, acc);
            }
            out[(size_t)B_SZ * C_IN + b * C_OUT + c] = 1.0f / (1.0f + expf(-acc));
        }
    }
}

extern "C" void kernel_launch(void* const* d_in, const int* in_sizes, int n_in,
                              void* d_out, int out_size) {
    const float* x            = (const float*)d_in[0];
    const float* fc_w         = (const float*)d_in[1];
    const float* bn_gamma     = (const float*)d_in[2];
    const float* bn_beta      = (const float*)d_in[3];
    const float* bn_mean      = (const float*)d_in[4];
    const float* bn_var       = (const float*)d_in[5];
    const float* channel_fc_w = (const float*)d_in[6];
    const float* channel_fc_b = (const float*)d_in[7];
    const float* filter_fc_w  = (const float*)d_in[8];
    const float* filter_fc_b  = (const float*)d_in[9];
    float* out = (float*)d_out;

    fused_kernel<<<B_SZ * BLOCKS_PER_B, 256>>>(
        x, fc_w, bn_gamma, bn_beta, bn_mean, bn_var,
        channel_fc_w, channel_fc_b, filter_fc_w, filter_fc_b, out);
}

// round 5
// speedup vs baseline: 1.1754x; 1.1754x over previous
#include <cuda_runtime.h>
#include <math.h>

// Problem constants (fixed shapes from reference)
#define HW     3136     // 56*56
#define HW4    784      // HW / 4 (float4 chunks per row)
#define B_SZ   64
#define C_IN   512
#define A_DIM  32
#define C_OUT  512
#define BN_EPS 1e-5f

// Scratch for pooled means: [B, C_in]
__device__ float g_pooled[B_SZ * C_IN];

// ---------------------------------------------------------------------------
// Kernel 1: global average pool. One warp per (b, c) row of 3136 floats.
// float4 loads, consecutive lanes -> consecutive 16B -> fully coalesced.
// 32768 rows / 8 warps per block = 4096 blocks. (~59us, ~87% of 8TB/s)
// IDENTICAL to R2 version — do not touch, it is near the HBM floor.
// ---------------------------------------------------------------------------
__global__ __launch_bounds__(256) void pool_kernel(const float* __restrict__ x) {
    const int gwarp = (blockIdx.x * blockDim.x + threadIdx.x) >> 5;
    const int lane  = threadIdx.x & 31;
    if (gwarp >= B_SZ * C_IN) return;

    const float4* __restrict__ row =
        reinterpret_cast<const float4*>(x + (size_t)gwarp * HW);

    float s0 = 0.f, s1 = 0.f;
    int i = lane;
    #pragma unroll 4
    for (; i + 32 < HW4; i += 64) {
        float4 v0 = __ldg(&row[i]);
        float4 v1 = __ldg(&row[i + 32]);
        s0 += (v0.x + v0.y) + (v0.z + v0.w);
        s1 += (v1.x + v1.y) + (v1.z + v1.w);
    }
    if (i < HW4) {
        float4 v0 = __ldg(&row[i]);
        s0 += (v0.x + v0.y) + (v0.z + v0.w);
    }
    float s = s0 + s1;

    #pragma unroll
    for (int off = 16; off > 0; off >>= 1)
        s += __shfl_xor_sync(0xFFFFFFFFu, s, off);

    if (lane == 0)
        g_pooled[gwarp] = s * (1.0f / (float)HW);
}

// ---------------------------------------------------------------------------
// Kernel 2: FC chain. Grid = 128 blocks: block (b, t) where t=0 -> channel
// attention, t=1 -> filter attention. 512 threads, one output per thread.
//
// Key latency trick: each thread PREFETCHES its 8 float4 attention weights
// into registers at kernel entry (cold DRAM ~600cyc), overlapping that with
// the pooled load (L2-hot) + h computation + barrier. h is recomputed by
// both blocks of a batch — 6 uFLOP of redundancy, free.
// ---------------------------------------------------------------------------
__global__ __launch_bounds__(512) void fc_kernel(
    const float* __restrict__ fc_w,         // [A, C_in]
    const float* __restrict__ bn_gamma,     // [A]
    const float* __restrict__ bn_beta,      // [A]
    const float* __restrict__ bn_mean,      // [A]
    const float* __restrict__ bn_var,       // [A]
    const float* __restrict__ channel_fc_w, // [C_in, A]
    const float* __restrict__ channel_fc_b, // [C_in]
    const float* __restrict__ filter_fc_w,  // [C_out, A]
    const float* __restrict__ filter_fc_b,  // [C_out]
    float* __restrict__ out)                // [2 * B * 512]
{
    __shared__ __align__(16) float s_pooled[C_IN];
    __shared__ __align__(16) float s_h[A_DIM];

    const int b    = blockIdx.x >> 1;
    const int t    = blockIdx.x & 1;        // 0 = channel, 1 = filter
    const int tid  = threadIdx.x;
    const int warp = tid >> 5;
    const int lane = tid & 31;

    // ---- prefetch this thread's attention weight row + bias (issue ASAP) ----
    const float* __restrict__ w_mat  = t ? filter_fc_w : channel_fc_w;
    const float* __restrict__ w_bias = t ? filter_fc_b : channel_fc_b;
    const float4* __restrict__ wrow =
        reinterpret_cast<const float4*>(w_mat + tid * A_DIM);
    float4 wv0 = __ldg(&wrow[0]);
    float4 wv1 = __ldg(&wrow[1]);
    float4 wv2 = __ldg(&wrow[2]);
    float4 wv3 = __ldg(&wrow[3]);
    float4 wv4 = __ldg(&wrow[4]);
    float4 wv5 = __ldg(&wrow[5]);
    float4 wv6 = __ldg(&wrow[6]);
    float4 wv7 = __ldg(&wrow[7]);
    float bias = __ldg(&w_bias[tid]);

    // ---- stage pooled row (L2-hot, written by pool_kernel) ----
    s_pooled[tid] = g_pooled[b * C_IN + tid];
    __syncthreads();

    // ---- h: warp w computes a = w and a = w+16 (warp-parallel dots) ----
    const float4* __restrict__ sp4 = reinterpret_cast<const float4*>(s_pooled);
    #pragma unroll
    for (int k = 0; k < 2; ++k) {
        const int a = warp + k * 16;
        const float4* __restrict__ w4 =
            reinterpret_cast<const float4*>(fc_w + a * C_IN);
        float acc = 0.f;
        #pragma unroll
        for (int j = 0; j < 4; ++j) {
            float4 wv = __ldg(&w4[lane + 32 * j]);
            float4 pv = sp4[lane + 32 * j];
            acc = fmaf(wv.x, pv.x, acc);
            acc = fmaf(wv.y, pv.y, acc);
            acc = fmaf(wv.z, pv.z, acc);
            acc = fmaf(wv.w, pv.w, acc);
        }
        #pragma unroll
        for (int off = 16; off > 0; off >>= 1)
            acc += __shfl_xor_sync(0xFFFFFFFFu, acc, off);
        if (lane == 0) {
            float inv_std = rsqrtf(bn_var[a] + BN_EPS);
            float hv = (acc - bn_mean[a]) * (bn_gamma[a] * inv_std) + bn_beta[a];
            s_h[a] = fmaxf(hv, 0.f);
        }
    }
    __syncthreads();

    // ---- attention output: dot(h, prefetched weights) -> sigmoid ----
    float acc = bias;
    acc = fmaf(s_h[0],  wv0.x, acc); acc = fmaf(s_h[1],  wv0.y, acc);
    acc = fmaf(s_h[2],  wv0.z, acc); acc = fmaf(s_h[3],  wv0.w, acc);
    acc = fmaf(s_h[4],  wv1.x, acc); acc = fmaf(s_h[5],  wv1.y, acc);
    acc = fmaf(s_h[6],  wv1.z, acc); acc = fmaf(s_h[7],  wv1.w, acc);
    acc = fmaf(s_h[8],  wv2.x, acc); acc = fmaf(s_h[9],  wv2.y, acc);
    acc = fmaf(s_h[10], wv2.z, acc); acc = fmaf(s_h[11], wv2.w, acc);
    acc = fmaf(s_h[12], wv3.x, acc); acc = fmaf(s_h[13], wv3.y, acc);
    acc = fmaf(s_h[14], wv3.z, acc); acc = fmaf(s_h[15], wv3.w, acc);
    acc = fmaf(s_h[16], wv4.x, acc); acc = fmaf(s_h[17], wv4.y, acc);
    acc = fmaf(s_h[18], wv4.z, acc); acc = fmaf(s_h[19], wv4.w, acc);
    acc = fmaf(s_h[20], wv5.x, acc); acc = fmaf(s_h[21], wv5.y, acc);
    acc = fmaf(s_h[22], wv5.z, acc); acc = fmaf(s_h[23], wv5.w, acc);
    acc = fmaf(s_h[24], wv6.x, acc); acc = fmaf(s_h[25], wv6.y, acc);
    acc = fmaf(s_h[26], wv6.z, acc); acc = fmaf(s_h[27], wv6.w, acc);
    acc = fmaf(s_h[28], wv7.x, acc); acc = fmaf(s_h[29], wv7.y, acc);
    acc = fmaf(s_h[30], wv7.z, acc); acc = fmaf(s_h[31], wv7.w, acc);

    const float sig = 1.0f / (1.0f + expf(-acc));
    // t=0: ch_att at [b*512 + tid]; t=1: f_att at [32768 + b*512 + tid]
    out[(size_t)t * (B_SZ * C_IN) + b * C_IN + tid] = sig;
}

extern "C" void kernel_launch(void* const* d_in, const int* in_sizes, int n_in,
                              void* d_out, int out_size) {
    const float* x            = (const float*)d_in[0];
    const float* fc_w         = (const float*)d_in[1];
    const float* bn_gamma     = (const float*)d_in[2];
    const float* bn_beta      = (const float*)d_in[3];
    const float* bn_mean      = (const float*)d_in[4];
    const float* bn_var       = (const float*)d_in[5];
    const float* channel_fc_w = (const float*)d_in[6];
    const float* channel_fc_b = (const float*)d_in[7];
    const float* filter_fc_w  = (const float*)d_in[8];
    const float* filter_fc_b  = (const float*)d_in[9];
    float* out = (float*)d_out;

    pool_kernel<<<(B_SZ * C_IN) / 8, 256>>>(x);

    fc_kernel<<<B_SZ * 2, 512>>>(fc_w, bn_gamma, bn_beta, bn_mean, bn_var,
                                 channel_fc_w, channel_fc_b,
                                 filter_fc_w, filter_fc_b, out);
}

// round 6
// speedup vs baseline: 1.1771x; 1.0014x over previous
#include <cuda_runtime.h>
#include <math.h>

// Problem constants (fixed shapes from reference)
#define HW     3136     // 56*56
#define HW4    784      // HW / 4 (float4 chunks per row)
#define B_SZ   64
#define C_IN   512
#define A_DIM  32
#define C_OUT  512
#define BN_EPS 1e-5f

// Scratch for pooled means: [B, C_in]
__device__ float g_pooled[B_SZ * C_IN];

// ---------------------------------------------------------------------------
// Kernel 1: global average pool. One warp per (b, c) row of 3136 floats.
// ~60us, ~86% of 8TB/s spec — near the HBM floor, unchanged from R2.
// ---------------------------------------------------------------------------
__global__ __launch_bounds__(256) void pool_kernel(const float* __restrict__ x) {
    const int gwarp = (blockIdx.x * blockDim.x + threadIdx.x) >> 5;
    const int lane  = threadIdx.x & 31;
    if (gwarp >= B_SZ * C_IN) return;

    const float4* __restrict__ row =
        reinterpret_cast<const float4*>(x + (size_t)gwarp * HW);

    float s0 = 0.f, s1 = 0.f;
    int i = lane;
    #pragma unroll 4
    for (; i + 32 < HW4; i += 64) {
        float4 v0 = __ldg(&row[i]);
        float4 v1 = __ldg(&row[i + 32]);
        s0 += (v0.x + v0.y) + (v0.z + v0.w);
        s1 += (v1.x + v1.y) + (v1.z + v1.w);
    }
    if (i < HW4) {
        float4 v0 = __ldg(&row[i]);
        s0 += (v0.x + v0.y) + (v0.z + v0.w);
    }
    float s = s0 + s1;

    #pragma unroll
    for (int off = 16; off > 0; off >>= 1)
        s += __shfl_xor_sync(0xFFFFFFFFu, s, off);

    if (lane == 0)
        g_pooled[gwarp] = s * (1.0f / (float)HW);
}

// ---------------------------------------------------------------------------
// Kernel 2: FC chain, PDL-overlapped with pool's tail.
// Grid = 128 blocks: block (b, t), t=0 -> channel att, t=1 -> filter att.
// ALL weight/param loads are issued at entry (one overlapped DRAM round
// trip, runs concurrently with pool under PDL); only g_pooled is read after
// cudaGridDependencySynchronize().
// ---------------------------------------------------------------------------
__global__ __launch_bounds__(512) void fc_kernel(
    const float* __restrict__ fc_w,         // [A, C_in]
    const float* __restrict__ bn_gamma,     // [A]
    const float* __restrict__ bn_beta,      // [A]
    const float* __restrict__ bn_mean,      // [A]
    const float* __restrict__ bn_var,       // [A]
    const float* __restrict__ channel_fc_w, // [C_in, A]
    const float* __restrict__ channel_fc_b, // [C_in]
    const float* __restrict__ filter_fc_w,  // [C_out, A]
    const float* __restrict__ filter_fc_b,  // [C_out]
    float* __restrict__ out)                // [2 * B * 512]
{
    __shared__ __align__(16) float s_pooled[C_IN];
    __shared__ __align__(16) float s_h[A_DIM];

    const int b    = blockIdx.x >> 1;
    const int t    = blockIdx.x & 1;        // 0 = channel, 1 = filter
    const int tid  = threadIdx.x;
    const int warp = tid >> 5;
    const int lane = tid & 31;

    // ======== PREAMBLE: issue every non-pooled load (overlaps pool) ========
    // attention weight row + bias for this thread's output
    const float* __restrict__ w_mat  = t ? filter_fc_w : channel_fc_w;
    const float* __restrict__ w_bias = t ? filter_fc_b : channel_fc_b;
    const float4* __restrict__ wrow =
        reinterpret_cast<const float4*>(w_mat + tid * A_DIM);
    float4 aw0 = __ldg(&wrow[0]); float4 aw1 = __ldg(&wrow[1]);
    float4 aw2 = __ldg(&wrow[2]); float4 aw3 = __ldg(&wrow[3]);
    float4 aw4 = __ldg(&wrow[4]); float4 aw5 = __ldg(&wrow[5]);
    float4 aw6 = __ldg(&wrow[6]); float4 aw7 = __ldg(&wrow[7]);
    float bias = __ldg(&w_bias[tid]);

    // fc_w values for this warp's two h-dots (a0 = warp, a1 = warp+16)
    const int a0 = warp, a1 = warp + 16;
    const float4* __restrict__ f0 =
        reinterpret_cast<const float4*>(fc_w + a0 * C_IN);
    const float4* __restrict__ f1 =
        reinterpret_cast<const float4*>(fc_w + a1 * C_IN);
    float4 fw00 = __ldg(&f0[lane]);      float4 fw01 = __ldg(&f0[lane + 32]);
    float4 fw02 = __ldg(&f0[lane + 64]); float4 fw03 = __ldg(&f0[lane + 96]);
    float4 fw10 = __ldg(&f1[lane]);      float4 fw11 = __ldg(&f1[lane + 32]);
    float4 fw12 = __ldg(&f1[lane + 64]); float4 fw13 = __ldg(&f1[lane + 96]);

    // bn params for both a values (broadcast loads, all lanes)
    float bnv0 = __ldg(&bn_var[a0]),  bnv1 = __ldg(&bn_var[a1]);
    float bnm0 = __ldg(&bn_mean[a0]), bnm1 = __ldg(&bn_mean[a1]);
    float bng0 = __ldg(&bn_gamma[a0]), bng1 = __ldg(&bn_gamma[a1]);
    float bnb0 = __ldg(&bn_beta[a0]), bnb1 = __ldg(&bn_beta[a1]);

    // ======== wait for pool_kernel (PDL programmatic dependency) ========
    cudaGridDependencySynchronize();

    // stage pooled row (L2-hot)
    s_pooled[tid] = g_pooled[b * C_IN + tid];
    __syncthreads();

    // ---- h: warp-parallel dots with pre-loaded fc_w ----
    const float4* __restrict__ sp4 = reinterpret_cast<const float4*>(s_pooled);
    float4 pv0 = sp4[lane];      float4 pv1 = sp4[lane + 32];
    float4 pv2 = sp4[lane + 64]; float4 pv3 = sp4[lane + 96];

    float acc0 = 0.f, acc1 = 0.f;
    acc0 = fmaf(fw00.x, pv0.x, acc0); acc0 = fmaf(fw00.y, pv0.y, acc0);
    acc0 = fmaf(fw00.z, pv0.z, acc0); acc0 = fmaf(fw00.w, pv0.w, acc0);
    acc0 = fmaf(fw01.x, pv1.x, acc0); acc0 = fmaf(fw01.y, pv1.y, acc0);
    acc0 = fmaf(fw01.z, pv1.z, acc0); acc0 = fmaf(fw01.w, pv1.w, acc0);
    acc0 = fmaf(fw02.x, pv2.x, acc0); acc0 = fmaf(fw02.y, pv2.y, acc0);
    acc0 = fmaf(fw02.z, pv2.z, acc0); acc0 = fmaf(fw02.w, pv2.w, acc0);
    acc0 = fmaf(fw03.x, pv3.x, acc0); acc0 = fmaf(fw03.y, pv3.y, acc0);
    acc0 = fmaf(fw03.z, pv3.z, acc0); acc0 = fmaf(fw03.w, pv3.w, acc0);

    acc1 = fmaf(fw10.x, pv0.x, acc1); acc1 = fmaf(fw10.y, pv0.y, acc1);
    acc1 = fmaf(fw10.z, pv0.z, acc1); acc1 = fmaf(fw10.w, pv0.w, acc1);
    acc1 = fmaf(fw11.x, pv1.x, acc1); acc1 = fmaf(fw11.y, pv1.y, acc1);
    acc1 = fmaf(fw11.z, pv1.z, acc1); acc1 = fmaf(fw11.w, pv1.w, acc1);
    acc1 = fmaf(fw12.x, pv2.x, acc1); acc1 = fmaf(fw12.y, pv2.y, acc1);
    acc1 = fmaf(fw12.z, pv2.z, acc1); acc1 = fmaf(fw12.w, pv2.w, acc1);
    acc1 = fmaf(fw13.x, pv3.x, acc1); acc1 = fmaf(fw13.y, pv3.y, acc1);
    acc1 = fmaf(fw13.z, pv3.z, acc1); acc1 = fmaf(fw13.w, pv3.w, acc1);

    #pragma unroll
    for (int off = 16; off > 0; off >>= 1) {
        acc0 += __shfl_xor_sync(0xFFFFFFFFu, acc0, off);
        acc1 += __shfl_xor_sync(0xFFFFFFFFu, acc1, off);
    }
    if (lane == 0) {
        float h0 = (acc0 - bnm0) * (bng0 * rsqrtf(bnv0 + BN_EPS)) + bnb0;
        float h1 = (acc1 - bnm1) * (bng1 * rsqrtf(bnv1 + BN_EPS)) + bnb1;
        s_h[a0] = fmaxf(h0, 0.f);
        s_h[a1] = fmaxf(h1, 0.f);
    }
    __syncthreads();

    // ---- attention output: dot(h, prefetched weights) -> sigmoid ----
    float acc = bias;
    acc = fmaf(s_h[0],  aw0.x, acc); acc = fmaf(s_h[1],  aw0.y, acc);
    acc = fmaf(s_h[2],  aw0.z, acc); acc = fmaf(s_h[3],  aw0.w, acc);
    acc = fmaf(s_h[4],  aw1.x, acc); acc = fmaf(s_h[5],  aw1.y, acc);
    acc = fmaf(s_h[6],  aw1.z, acc); acc = fmaf(s_h[7],  aw1.w, acc);
    acc = fmaf(s_h[8],  aw2.x, acc); acc = fmaf(s_h[9],  aw2.y, acc);
    acc = fmaf(s_h[10], aw2.z, acc); acc = fmaf(s_h[11], aw2.w, acc);
    acc = fmaf(s_h[12], aw3.x, acc); acc = fmaf(s_h[13], aw3.y, acc);
    acc = fmaf(s_h[14], aw3.z, acc); acc = fmaf(s_h[15], aw3.w, acc);
    acc = fmaf(s_h[16], aw4.x, acc); acc = fmaf(s_h[17], aw4.y, acc);
    acc = fmaf(s_h[18], aw4.z, acc); acc = fmaf(s_h[19], aw4.w, acc);
    acc = fmaf(s_h[20], aw5.x, acc); acc = fmaf(s_h[21], aw5.y, acc);
    acc = fmaf(s_h[22], aw5.z, acc); acc = fmaf(s_h[23], aw5.w, acc);
    acc = fmaf(s_h[24], aw6.x, acc); acc = fmaf(s_h[25], aw6.y, acc);
    acc = fmaf(s_h[26], aw6.z, acc); acc = fmaf(s_h[27], aw6.w, acc);
    acc = fmaf(s_h[28], aw7.x, acc); acc = fmaf(s_h[29], aw7.y, acc);
    acc = fmaf(s_h[30], aw7.z, acc); acc = fmaf(s_h[31], aw7.w, acc);

    out[(size_t)t * (B_SZ * C_IN) + b * C_IN + tid] =
        1.0f / (1.0f + expf(-acc));
}

extern "C" void kernel_launch(void* const* d_in, const int* in_sizes, int n_in,
                              void* d_out, int out_size) {
    const float* x            = (const float*)d_in[0];
    const float* fc_w         = (const float*)d_in[1];
    const float* bn_gamma     = (const float*)d_in[2];
    const float* bn_beta      = (const float*)d_in[3];
    const float* bn_mean      = (const float*)d_in[4];
    const float* bn_var       = (const float*)d_in[5];
    const float* channel_fc_w = (const float*)d_in[6];
    const float* channel_fc_b = (const float*)d_in[7];
    const float* filter_fc_w  = (const float*)d_in[8];
    const float* filter_fc_b  = (const float*)d_in[9];
    float* out = (float*)d_out;

    pool_kernel<<<(B_SZ * C_IN) / 8, 256>>>(x);

    // PDL launch: fc blocks start during pool's tail wave, run the weight
    // prefetch preamble concurrently, then wait on the programmatic edge.
    cudaLaunchConfig_t cfg = {};
    cfg.gridDim  = dim3(B_SZ * 2);
    cfg.blockDim = dim3(512);
    cfg.dynamicSmemBytes = 0;
    cfg.stream = 0;
    cudaLaunchAttribute attr[1];
    attr[0].id = cudaLaunchAttributeProgrammaticStreamSerialization;
    attr[0].val.programmaticStreamSerializationAllowed = 1;
    cfg.attrs = attr;
    cfg.numAttrs = 1;
    cudaLaunchKernelEx(&cfg, fc_kernel,
                       fc_w, bn_gamma, bn_beta, bn_mean, bn_var,
                       channel_fc_w, channel_fc_b,
                       filter_fc_w, filter_fc_b, out);
}

// round 7
// speedup vs baseline: 1.2113x; 1.0291x over previous
#include <cuda_runtime.h>
#include <math.h>

// Problem constants (fixed shapes from reference)
#define HW     3136     // 56*56
#define HW4    784      // HW / 4 (float4 chunks per row)
#define B_SZ   64
#define C_IN   512
#define A_DIM  32
#define C_OUT  512
#define BN_EPS 1e-5f

// fc kernel dynamic smem layout (floats):
//   s_wT  : [32][513] transposed attention-weight tile (padded, 16416 floats)
//   s_pooled : [512]
//   s_h      : [32]
#define SWT_STRIDE 513
#define SMEM_FLOATS (A_DIM * SWT_STRIDE + C_IN + A_DIM)

// Scratch for pooled means: [B, C_in]
__device__ float g_pooled[B_SZ * C_IN];

// ---------------------------------------------------------------------------
// Kernel 1: global average pool. One warp per (b, c) row of 3136 floats.
// ~60us, ~86% of 8TB/s spec — near the HBM floor, unchanged since R2.
// ---------------------------------------------------------------------------
__global__ __launch_bounds__(256) void pool_kernel(const float* __restrict__ x) {
    const int gwarp = (blockIdx.x * blockDim.x + threadIdx.x) >> 5;
    const int lane  = threadIdx.x & 31;
    if (gwarp >= B_SZ * C_IN) return;

    const float4* __restrict__ row =
        reinterpret_cast<const float4*>(x + (size_t)gwarp * HW);

    float s0 = 0.f, s1 = 0.f;
    int i = lane;
    #pragma unroll 4
    for (; i + 32 < HW4; i += 64) {
        float4 v0 = __ldg(&row[i]);
        float4 v1 = __ldg(&row[i + 32]);
        s0 += (v0.x + v0.y) + (v0.z + v0.w);
        s1 += (v1.x + v1.y) + (v1.z + v1.w);
    }
    if (i < HW4) {
        float4 v0 = __ldg(&row[i]);
        s0 += (v0.x + v0.y) + (v0.z + v0.w);
    }
    float s = s0 + s1;

    #pragma unroll
    for (int off = 16; off > 0; off >>= 1)
        s += __shfl_xor_sync(0xFFFFFFFFu, s, off);

    if (lane == 0)
        g_pooled[gwarp] = s * (1.0f / (float)HW);
}

// ---------------------------------------------------------------------------
// Kernel 2: FC chain. Grid = 128 blocks: block (b, t), t=0 channel / t=1
// filter. 512 threads, one output per thread.
//
// Attention weights [512 x 32] are staged into smem TRANSPOSED via fully
// coalesced float4 loads (4 lines / warp-LDG instead of 32 -> ~6x fewer
// L1tex wavefronts than row-per-thread). Padding 513 makes both the
// scattered STS and the column LDS bank-conflict-free.
// ---------------------------------------------------------------------------
__global__ __launch_bounds__(512) void fc_kernel(
    const float* __restrict__ fc_w,         // [A, C_in]
    const float* __restrict__ bn_gamma,     // [A]
    const float* __restrict__ bn_beta,      // [A]
    const float* __restrict__ bn_mean,      // [A]
    const float* __restrict__ bn_var,       // [A]
    const float* __restrict__ channel_fc_w, // [C_in, A]
    const float* __restrict__ channel_fc_b, // [C_in]
    const float* __restrict__ filter_fc_w,  // [C_out, A]
    const float* __restrict__ filter_fc_b,  // [C_out]
    float* __restrict__ out)                // [2 * B * 512]
{
    extern __shared__ __align__(16) float smem[];
    float* s_wT     = smem;                          // [32][513]
    float* s_pooled = smem + A_DIM * SWT_STRIDE;     // [512] (offset 65664B, 16B aligned)
    float* s_h      = s_pooled + C_IN;               // [32]

    const int b    = blockIdx.x >> 1;
    const int t    = blockIdx.x & 1;        // 0 = channel, 1 = filter
    const int tid  = threadIdx.x;
    const int warp = tid >> 5;
    const int lane = tid & 31;

    // ======== PREAMBLE (overlaps pool via PDL) ========
    // Stage attention weight tile coalesced -> transposed smem.
    const float* __restrict__ w_mat  = t ? filter_fc_w : channel_fc_w;
    const float* __restrict__ w_bias = t ? filter_fc_b : channel_fc_b;
    const float4* __restrict__ g4 = reinterpret_cast<const float4*>(w_mat);
    #pragma unroll
    for (int k = 0; k < 8; ++k) {
        const int i = tid + k * 512;         // float4 index, lanes contiguous
        float4 v = __ldg(&g4[i]);
        const int f = i << 2;                // first float index
        const int c = f >> 5;                // output row (0..511)
        const int a = f & 31;                // a-offset (multiple of 4)
        s_wT[(a + 0) * SWT_STRIDE + c] = v.x;
        s_wT[(a + 1) * SWT_STRIDE + c] = v.y;
        s_wT[(a + 2) * SWT_STRIDE + c] = v.z;
        s_wT[(a + 3) * SWT_STRIDE + c] = v.w;
    }
    float bias = __ldg(&w_bias[tid]);

    // fc_w rows for this warp's two h-dots (coalesced, 4 lines per LDG)
    const int a0 = warp, a1 = warp + 16;
    const float4* __restrict__ f0 =
        reinterpret_cast<const float4*>(fc_w + a0 * C_IN);
    const float4* __restrict__ f1 =
        reinterpret_cast<const float4*>(fc_w + a1 * C_IN);
    float4 fw00 = __ldg(&f0[lane]);      float4 fw01 = __ldg(&f0[lane + 32]);
    float4 fw02 = __ldg(&f0[lane + 64]); float4 fw03 = __ldg(&f0[lane + 96]);
    float4 fw10 = __ldg(&f1[lane]);      float4 fw11 = __ldg(&f1[lane + 32]);
    float4 fw12 = __ldg(&f1[lane + 64]); float4 fw13 = __ldg(&f1[lane + 96]);

    float bnv0 = __ldg(&bn_var[a0]),   bnv1 = __ldg(&bn_var[a1]);
    float bnm0 = __ldg(&bn_mean[a0]),  bnm1 = __ldg(&bn_mean[a1]);
    float bng0 = __ldg(&bn_gamma[a0]), bng1 = __ldg(&bn_gamma[a1]);
    float bnb0 = __ldg(&bn_beta[a0]),  bnb1 = __ldg(&bn_beta[a1]);

    // ======== wait for pool_kernel (PDL edge) ========
    cudaGridDependencySynchronize();

    s_pooled[tid] = g_pooled[b * C_IN + tid];
    __syncthreads();

    // ---- h: warp-parallel dots with pre-loaded fc_w ----
    const float4* __restrict__ sp4 = reinterpret_cast<const float4*>(s_pooled);
    float4 pv0 = sp4[lane];      float4 pv1 = sp4[lane + 32];
    float4 pv2 = sp4[lane + 64]; float4 pv3 = sp4[lane + 96];

    float acc0 = 0.f, acc1 = 0.f;
    acc0 = fmaf(fw00.x, pv0.x, acc0); acc0 = fmaf(fw00.y, pv0.y, acc0);
    acc0 = fmaf(fw00.z, pv0.z, acc0); acc0 = fmaf(fw00.w, pv0.w, acc0);
    acc0 = fmaf(fw01.x, pv1.x, acc0); acc0 = fmaf(fw01.y, pv1.y, acc0);
    acc0 = fmaf(fw01.z, pv1.z, acc0); acc0 = fmaf(fw01.w, pv1.w, acc0);
    acc0 = fmaf(fw02.x, pv2.x, acc0); acc0 = fmaf(fw02.y, pv2.y, acc0);
    acc0 = fmaf(fw02.z, pv2.z, acc0); acc0 = fmaf(fw02.w, pv2.w, acc0);
    acc0 = fmaf(fw03.x, pv3.x, acc0); acc0 = fmaf(fw03.y, pv3.y, acc0);
    acc0 = fmaf(fw03.z, pv3.z, acc0); acc0 = fmaf(fw03.w, pv3.w, acc0);

    acc1 = fmaf(fw10.x, pv0.x, acc1); acc1 = fmaf(fw10.y, pv0.y, acc1);
    acc1 = fmaf(fw10.z, pv0.z, acc1); acc1 = fmaf(fw10.w, pv0.w, acc1);
    acc1 = fmaf(fw11.x, pv1.x, acc1); acc1 = fmaf(fw11.y, pv1.y, acc1);
    acc1 = fmaf(fw11.z, pv1.z, acc1); acc1 = fmaf(fw11.w, pv1.w, acc1);
    acc1 = fmaf(fw12.x, pv2.x, acc1); acc1 = fmaf(fw12.y, pv2.y, acc1);
    acc1 = fmaf(fw12.z, pv2.z, acc1); acc1 = fmaf(fw12.w, pv2.w, acc1);
    acc1 = fmaf(fw13.x, pv3.x, acc1); acc1 = fmaf(fw13.y, pv3.y, acc1);
    acc1 = fmaf(fw13.z, pv3.z, acc1); acc1 = fmaf(fw13.w, pv3.w, acc1);

    #pragma unroll
    for (int off = 16; off > 0; off >>= 1) {
        acc0 += __shfl_xor_sync(0xFFFFFFFFu, acc0, off);
        acc1 += __shfl_xor_sync(0xFFFFFFFFu, acc1, off);
    }
    if (lane == 0) {
        float h0 = (acc0 - bnm0) * (bng0 * rsqrtf(bnv0 + BN_EPS)) + bnb0;
        float h1 = (acc1 - bnm1) * (bng1 * rsqrtf(bnv1 + BN_EPS)) + bnb1;
        s_h[a0] = fmaxf(h0, 0.f);
        s_h[a1] = fmaxf(h1, 0.f);
    }
    __syncthreads();

    // ---- attention output: dot over smem-transposed weights ----
    // LDS s_wT[a*513 + tid]: lanes contiguous -> banks (a+tid)%32 distinct.
    float acc = bias;
    #pragma unroll
    for (int a = 0; a < A_DIM; ++a)
        acc = fmaf(s_h[a], s_wT[a * SWT_STRIDE + tid], acc);

    out[(size_t)t * (B_SZ * C_IN) + b * C_IN + tid] =
        1.0f / (1.0f + expf(-acc));
}

extern "C" void kernel_launch(void* const* d_in, const int* in_sizes, int n_in,
                              void* d_out, int out_size) {
    const float* x            = (const float*)d_in[0];
    const float* fc_w         = (const float*)d_in[1];
    const float* bn_gamma     = (const float*)d_in[2];
    const float* bn_beta      = (const float*)d_in[3];
    const float* bn_mean      = (const float*)d_in[4];
    const float* bn_var       = (const float*)d_in[5];
    const float* channel_fc_w = (const float*)d_in[6];
    const float* channel_fc_b = (const float*)d_in[7];
    const float* filter_fc_w  = (const float*)d_in[8];
    const float* filter_fc_b  = (const float*)d_in[9];
    float* out = (float*)d_out;

    const int smem_bytes = SMEM_FLOATS * (int)sizeof(float);
    static bool attr_set = false;   // host-side only; idempotent runtime attr
    if (!attr_set) {
        cudaFuncSetAttribute(fc_kernel,
                             cudaFuncAttributeMaxDynamicSharedMemorySize,
                             smem_bytes);
        attr_set = true;
    }

    pool_kernel<<<(B_SZ * C_IN) / 8, 256>>>(x);

    cudaLaunchConfig_t cfg = {};
    cfg.gridDim  = dim3(B_SZ * 2);
    cfg.blockDim = dim3(512);
    cfg.dynamicSmemBytes = smem_bytes;
    cfg.stream = 0;
    cudaLaunchAttribute attr[1];
    attr[0].id = cudaLaunchAttributeProgrammaticStreamSerialization;
    attr[0].val.programmaticStreamSerializationAllowed = 1;
    cfg.attrs = attr;
    cfg.numAttrs = 1;
    cudaLaunchKernelEx(&cfg, fc_kernel,
                       fc_w, bn_gamma, bn_beta, bn_mean, bn_var,
                       channel_fc_w, channel_fc_b,
                       filter_fc_w, filter_fc_b, out);
}